// round 12
// baseline (speedup 1.0000x reference)
#include <cuda_runtime.h>
#include <math.h>

// Problem constants
#define Bn   32
#define Cn   16
#define HWn  65536
#define T1   128               // pass1 tiles per batch (512 px/tile)
#define T3   128               // pass3 tiles per batch (512 px/tile)
#define PPB  512
#define THR  128
#define NB   592               // persistent blocks = 4/SM x 148 (co-resident)
#define NA_ITEMS (T1 * Bn * 2) // 8192 phase-A work items
#define NB_ITEMS (T3 * Bn)     // 4096 phase-B work items

// Scratch (__device__ globals; fully overwritten each run)
__device__ float g_part[2][Bn][32][T1];
__device__ float g_cnt[Bn][T1];
__device__ float g_dm[2][Bn][Cn];
__device__ float g_msep[1024];
__device__ unsigned int g_bar1;    // phase-A completion counter
__device__ unsigned int g_bar2;    // dM-ready counter (64 arrivals)
__device__ unsigned int g_done;    // MSE last-block counter

__device__ __forceinline__ float wred(float v) {
    v += __shfl_down_sync(0xFFFFFFFFu, v, 16);
    v += __shfl_down_sync(0xFFFFFFFFu, v, 8);
    v += __shfl_down_sync(0xFFFFFFFFu, v, 4);
    v += __shfl_down_sync(0xFFFFFFFFu, v, 2);
    v += __shfl_down_sync(0xFFFFFFFFu, v, 1);
    return v;
}
__device__ __forceinline__ double wredd(double v) {
    v += __shfl_down_sync(0xFFFFFFFFu, v, 16);
    v += __shfl_down_sync(0xFFFFFFFFu, v, 8);
    v += __shfl_down_sync(0xFFFFFFFFu, v, 4);
    v += __shfl_down_sync(0xFFFFFFFFu, v, 2);
    v += __shfl_down_sync(0xFFFFFFFFu, v, 1);
    return v;
}
__device__ __forceinline__ float4 ldcs4(const float* p) {
    return __ldcs((const float4*)p);
}

__device__ __forceinline__ int sniff_is32(const int* __restrict__ tw, int tid) {
    int any = 0;
#pragma unroll
    for (int i = tid; i < 512; i += THR) any |= tw[2 * i + 1];
    return __syncthreads_or(any);
}

__device__ __forceinline__ void load_cls4(const int* __restrict__ twb, int p, int is32,
                                          int& c0, int& c1, int& c2, int& c3) {
    if (is32) {
        int4 v = __ldg((const int4*)(twb + p));
        c0 = v.x; c1 = v.y; c2 = v.z; c3 = v.w;
    } else {
        int4 a = __ldg((const int4*)(twb + 2 * p));
        int4 b = __ldg((const int4*)(twb + 2 * p + 4));
        c0 = a.x; c1 = a.z; c2 = b.x; c3 = b.z;
    }
}

// Arrive (one per block) then spin until counter reaches target.
__device__ __forceinline__ void grid_barrier(unsigned int* ctr, unsigned int target,
                                             int tid, int arrive) {
    __threadfence();
    __syncthreads();
    if (tid == 0) {
        if (arrive) atomicAdd(ctr, 1u);
        while (atomicAdd(ctr, 0u) < target) __nanosleep(128);
    }
    __syncthreads();
    __threadfence();
}

// ---------------------------------------------------------------------------
// Fused persistent kernel: phase A (pass1) -> barrier -> parallel finalize ->
// barrier -> phase B (pass3) -> last-block MSE writeout + counter reset.
// ---------------------------------------------------------------------------
__global__ void __launch_bounds__(THR, 4)
fused_kernel(const float* __restrict__ S, const float* __restrict__ T,
             const int* __restrict__ TW, float* __restrict__ out) {
    const int bid = blockIdx.x;
    const int tid = threadIdx.x;
    const int lane = tid & 31, w = tid >> 5;
    const int is32 = sniff_is32(TW, tid);

    __shared__ float sred[THR / 32][33];

    // ======================= Phase A: pass1 =======================
    for (int id = bid; id < NA_ITEMS; id += NB) {
        const int z = id >> 12;
        const int b = (id >> 7) & 31;
        const int tile = id & 127;

        const float* Xb  = (z ? T : S) + ((size_t)b << 20);
        const int*   twb = TW + (is32 ? ((size_t)b << 16) : ((size_t)b << 17));

        const int p = tile * PPB + tid * 4;
        int c0, c1, c2, c3;
        load_cls4(twb, p, is32, c0, c1, c2, c3);
        const float m0 = (c0 == 0) ? 1.f : 0.f;
        const float m1 = (c1 == 0) ? 1.f : 0.f;
        const float m2 = (c2 == 0) ? 1.f : 0.f;
        const float m3 = (c3 == 0) ? 1.f : 0.f;
        float cnt = (m0 + m1) + (m2 + m3);

        float4 v[Cn];
#pragma unroll
        for (int c = 0; c < Cn; c++) v[c] = ldcs4(Xb + ((size_t)c << 16) + p);

        float n0 = 0.f, n1 = 0.f, n2 = 0.f, n3 = 0.f;
#pragma unroll
        for (int c = 0; c < Cn; c++) {
            n0 = fmaf(v[c].x, v[c].x, n0); n1 = fmaf(v[c].y, v[c].y, n1);
            n2 = fmaf(v[c].z, v[c].z, n2); n3 = fmaf(v[c].w, v[c].w, n3);
        }
        const float i0 = rsqrtf(fmaxf(n0, 1e-24f));
        const float i1 = rsqrtf(fmaxf(n1, 1e-24f));
        const float i2 = rsqrtf(fmaxf(n2, 1e-24f));
        const float i3 = rsqrtf(fmaxf(n3, 1e-24f));

        float at[Cn], a0[Cn];
#pragma unroll
        for (int c = 0; c < Cn; c++) {
            const float f0 = v[c].x * i0, f1 = v[c].y * i1;
            const float f2 = v[c].z * i2, f3 = v[c].w * i3;
            at[c] = (f0 + f1) + (f2 + f3);
            a0[c] = (m0 * f0 + m1 * f1) + (m2 * f2 + m3 * f3);
        }

#pragma unroll
        for (int c = 0; c < Cn; c++) { at[c] = wred(at[c]); a0[c] = wred(a0[c]); }
        cnt = wred(cnt);
        if (lane == 0) {
#pragma unroll
            for (int c = 0; c < Cn; c++) { sred[w][c] = at[c]; sred[w][16 + c] = a0[c]; }
            sred[w][32] = cnt;
        }
        __syncthreads();
        if (tid < 33) {
            float s = 0.f;
#pragma unroll
            for (int ww = 0; ww < THR / 32; ww++) s += sred[ww][tid];
            if (tid < 32)      g_part[z][b][tid][tile] = s;
            else if (z == 0)   g_cnt[b][tile] = s;
        }
        __syncthreads();   // protect sred reuse next iteration
    }

    // =================== Barrier 1: all phase-A done ===================
    grid_barrier(&g_bar1, NB, tid, 1);

    // ============ Parallel finalize: blocks 0..63, one (z,b) each ============
    if (bid < 64) {
        const int z = bid >> 5, b = bid & 31;
        __shared__ float sg[4][32];
        __shared__ float sgc[4];
        __shared__ float red[32];
        __shared__ float scnt;
        __shared__ float smean[2][Cn];
        __shared__ float srn[2];
        {   // 128 threads = 32 slots x 4 groups of 32 tiles
            const int slot = tid & 31, g = tid >> 5;
            const float* base = &g_part[z][b][slot][0] + g * 32;
            float a = 0.f;
#pragma unroll
            for (int k = 0; k < 8; k++) {
                const float4 vv = *(const float4*)(base + 4 * k);
                a += (vv.x + vv.y) + (vv.z + vv.w);
            }
            sg[g][slot] = a;
        }
        if (tid < 4) {
            const float* cb = &g_cnt[b][0] + tid * 32;
            float a = 0.f;
#pragma unroll
            for (int k = 0; k < 8; k++) {
                const float4 vv = *(const float4*)(cb + 4 * k);
                a += (vv.x + vv.y) + (vv.z + vv.w);
            }
            sgc[tid] = a;
        }
        __syncthreads();
        if (tid < 32) {
            red[tid] = ((sg[0][tid] + sg[1][tid]) + (sg[2][tid] + sg[3][tid]));
        } else if (tid == 32) {
            scnt = (sgc[0] + sgc[1]) + (sgc[2] + sgc[3]);
        }
        __syncthreads();
        if (tid < 2) {
            const int cls = tid;
            const float cnt0 = scnt;
            const float cv   = cls ? ((float)HWn - cnt0) : cnt0;
            const float inv  = 1.0f / (cv + 1e-6f);
            float nm2 = 0.f;
#pragma unroll
            for (int c = 0; c < Cn; c++) {
                const float tot = red[c], s0 = red[16 + c];
                const float sv  = cls ? (tot - s0) : s0;
                const float m   = sv * inv;
                smean[cls][c] = m;
                nm2 = fmaf(m, m, nm2);
            }
            srn[cls] = 1.0f / fmaxf(sqrtf(nm2), 1e-8f);
        }
        __syncthreads();
        if (tid < Cn)
            g_dm[z][b][tid] = smean[0][tid] * srn[0] - smean[1][tid] * srn[1];
        grid_barrier(&g_bar2, 64, tid, 1);
    } else {
        grid_barrier(&g_bar2, 64, tid, 0);
    }

    // ======================= Phase B: pass3 =======================
    float acc = 0.f;
    for (int id = bid; id < NB_ITEMS; id += NB) {
        const int b = id >> 7;
        const int tile = id & 127;

        const float* Sb  = S + ((size_t)b << 20);
        const float* Tb  = T + ((size_t)b << 20);
        const int*   twb = TW + (is32 ? ((size_t)b << 16) : ((size_t)b << 17));

        const int p = tile * PPB + tid * 4;
        int c0, c1, c2, c3;
        load_cls4(twb, p, is32, c0, c1, c2, c3);
        const float s0 = (c0 == 0) ? 1.f : -1.f;
        const float s1 = (c1 == 0) ? 1.f : -1.f;
        const float s2 = (c2 == 0) ? 1.f : -1.f;
        const float s3 = (c3 == 0) ? 1.f : -1.f;

        float nS0 = 0.f, nS1 = 0.f, nS2 = 0.f, nS3 = 0.f;
        float dS0 = 0.f, dS1 = 0.f, dS2 = 0.f, dS3 = 0.f;
        float nT0 = 0.f, nT1 = 0.f, nT2 = 0.f, nT3 = 0.f;
        float dT0 = 0.f, dT1 = 0.f, dT2 = 0.f, dT3 = 0.f;
#pragma unroll
        for (int c = 0; c < Cn; c++) {
            const float4 vs = ldcs4(Sb + ((size_t)c << 16) + p);
            const float4 vt = ldcs4(Tb + ((size_t)c << 16) + p);
            const float mS = __ldg(&g_dm[0][b][c]);
            const float mT = __ldg(&g_dm[1][b][c]);
            nS0 = fmaf(vs.x, vs.x, nS0); nS1 = fmaf(vs.y, vs.y, nS1);
            nS2 = fmaf(vs.z, vs.z, nS2); nS3 = fmaf(vs.w, vs.w, nS3);
            dS0 = fmaf(vs.x, mS, dS0);   dS1 = fmaf(vs.y, mS, dS1);
            dS2 = fmaf(vs.z, mS, dS2);   dS3 = fmaf(vs.w, mS, dS3);
            nT0 = fmaf(vt.x, vt.x, nT0); nT1 = fmaf(vt.y, vt.y, nT1);
            nT2 = fmaf(vt.z, vt.z, nT2); nT3 = fmaf(vt.w, vt.w, nT3);
            dT0 = fmaf(vt.x, mT, dT0);   dT1 = fmaf(vt.y, mT, dT1);
            dT2 = fmaf(vt.z, mT, dT2);   dT3 = fmaf(vt.w, mT, dT3);
        }

        const float e0 = __expf(s0 * dS0 * rsqrtf(fmaxf(nS0, 1e-24f)))
                       - __expf(s0 * dT0 * rsqrtf(fmaxf(nT0, 1e-24f)));
        const float e1 = __expf(s1 * dS1 * rsqrtf(fmaxf(nS1, 1e-24f)))
                       - __expf(s1 * dT1 * rsqrtf(fmaxf(nT1, 1e-24f)));
        const float e2 = __expf(s2 * dS2 * rsqrtf(fmaxf(nS2, 1e-24f)))
                       - __expf(s2 * dT2 * rsqrtf(fmaxf(nT2, 1e-24f)));
        const float e3 = __expf(s3 * dS3 * rsqrtf(fmaxf(nS3, 1e-24f)))
                       - __expf(s3 * dT3 * rsqrtf(fmaxf(nT3, 1e-24f)));
        acc += fmaf(e0, e0, e1 * e1) + fmaf(e2, e2, e3 * e3);
    }

    // ============ Block reduce MSE, last block writes + resets ============
    __shared__ float smse[THR / 32];
    __shared__ unsigned int slast;
    acc = wred(acc);
    if (lane == 0) smse[w] = acc;
    __syncthreads();
    if (tid == 0) {
        float sv = 0.f;
#pragma unroll
        for (int ww = 0; ww < THR / 32; ww++) sv += smse[ww];
        g_msep[bid] = sv;
        __threadfence();
        const unsigned int old = atomicAdd(&g_done, 1u);
        slast = (old == (unsigned int)(NB - 1)) ? 1u : 0u;
    }
    __syncthreads();

    if (slast) {
        volatile float* mp = &g_msep[0];
        double d = 0.0;
        for (int k = tid; k < NB; k += THR) d += (double)mp[k];
        d = wredd(d);
        __shared__ double sd[THR / 32];
        if (lane == 0) sd[w] = d;
        __syncthreads();
        if (tid == 0) {
            double tot = 0.0;
#pragma unroll
            for (int ww = 0; ww < THR / 32; ww++) tot += sd[ww];
            out[0] = (float)(tot * (1.0 / ((double)Bn * (double)HWn)));
            g_bar1 = 0; g_bar2 = 0; g_done = 0;   // reset for graph replay
        }
    }
}

extern "C" void kernel_launch(void* const* d_in, const int* in_sizes, int n_in,
                              void* d_out, int out_size) {
    const float* S  = (const float*)d_in[0];
    const float* T  = (const float*)d_in[1];
    const int*   TW = (const int*)d_in[2];
    float* out = (float*)d_out;

    fused_kernel<<<NB, THR>>>(S, T, TW, out);
}

// round 13
// speedup vs baseline: 1.0003x; 1.0003x over previous
#include <cuda_runtime.h>
#include <math.h>

// Problem constants
#define Bn   32
#define Cn   16
#define HWn  65536
#define T1   128               // tiles per batch, pass1 (512 px/tile)
#define T3   128               // tiles per batch, pass3 (512 px/tile)
#define PPB  512               // pixels per block
#define THR  128               // threads per block; 4 px/thread, float4

// Scratch (__device__ globals; fully overwritten each run)
__device__ float g_part[2][Bn][32][T1];   // [tensor][batch][slot:0-15 tot,16-31 cls0][tile]
__device__ float g_cnt[Bn][T1];           // class-0 count partials (z==0)
__device__ float g_dm[2][Bn][Cn];         // normalized mean difference vectors
__device__ unsigned int g_cls[Bn][HWn / 4]; // packed class-0 flags, 1 byte/px
__device__ float g_msep[Bn * T3];         // per-block MSE partials
__device__ unsigned int g_done;           // last-block counter (self-resetting)

__device__ __forceinline__ float wred(float v) {
    v += __shfl_down_sync(0xFFFFFFFFu, v, 16);
    v += __shfl_down_sync(0xFFFFFFFFu, v, 8);
    v += __shfl_down_sync(0xFFFFFFFFu, v, 4);
    v += __shfl_down_sync(0xFFFFFFFFu, v, 2);
    v += __shfl_down_sync(0xFFFFFFFFu, v, 1);
    return v;
}
__device__ __forceinline__ double wredd(double v) {
    v += __shfl_down_sync(0xFFFFFFFFu, v, 16);
    v += __shfl_down_sync(0xFFFFFFFFu, v, 8);
    v += __shfl_down_sync(0xFFFFFFFFu, v, 4);
    v += __shfl_down_sync(0xFFFFFFFFu, v, 2);
    v += __shfl_down_sync(0xFFFFFFFFu, v, 1);
    return v;
}
__device__ __forceinline__ float4 ldcs4(const float* p) {
    return __ldcs((const float4*)p);
}

// Per-block dtype sniff (pass1 only): int64 targets with values in {0,1} have
// all odd 32-bit words zero; int32 targets have random labels there. All
// blocks read the same 512 words (L2-broadcast) -> identical result.
__device__ __forceinline__ int sniff_is32(const int* __restrict__ tw, int tid) {
    int any = 0;
#pragma unroll
    for (int i = tid; i < 512; i += THR) any |= tw[2 * i + 1];
    return __syncthreads_or(any);
}

__device__ __forceinline__ void load_cls4(const int* __restrict__ twb, int p, int is32,
                                          int& c0, int& c1, int& c2, int& c3) {
    if (is32) {
        int4 v = __ldg((const int4*)(twb + p));
        c0 = v.x; c1 = v.y; c2 = v.z; c3 = v.w;
    } else {
        int4 a = __ldg((const int4*)(twb + 2 * p));
        int4 b = __ldg((const int4*)(twb + 2 * p + 4));
        c0 = a.x; c1 = a.z; c2 = b.x; c3 = b.z;
    }
}

// ---------------------------------------------------------------------------
// Pass 1: partial sums of L2-normalized features + packed class-code emission
// (z==0 only; one coalesced STG.32 per thread). grid (T1, Bn, 2).
// ---------------------------------------------------------------------------
__global__ void __launch_bounds__(THR, 4)
pass1_kernel(const float* __restrict__ S, const float* __restrict__ T,
             const int* __restrict__ TW) {
    const int tile = blockIdx.x, b = blockIdx.y, z = blockIdx.z;
    const int tid  = threadIdx.x;
    const int is32 = sniff_is32(TW, tid);

    const float* Xb  = (z ? T : S) + ((size_t)b << 20);
    const int*   twb = TW + (is32 ? ((size_t)b << 16) : ((size_t)b << 17));

    const int p = tile * PPB + tid * 4;
    int c0, c1, c2, c3;
    load_cls4(twb, p, is32, c0, c1, c2, c3);
    const float m0 = (c0 == 0) ? 1.f : 0.f;
    const float m1 = (c1 == 0) ? 1.f : 0.f;
    const float m2 = (c2 == 0) ? 1.f : 0.f;
    const float m3 = (c3 == 0) ? 1.f : 0.f;
    float cnt = (m0 + m1) + (m2 + m3);

    // Packed class codes: byte k = 1 if pixel p+k is class 0.
    if (z == 0) {
        const unsigned int pack = (c0 == 0 ? 1u : 0u)
                                | (c1 == 0 ? 1u << 8 : 0u)
                                | (c2 == 0 ? 1u << 16 : 0u)
                                | (c3 == 0 ? 1u << 24 : 0u);
        g_cls[b][p >> 2] = pack;
    }

    float4 v[Cn];
#pragma unroll
    for (int c = 0; c < Cn; c++) v[c] = ldcs4(Xb + ((size_t)c << 16) + p);

    float n0 = 0.f, n1 = 0.f, n2 = 0.f, n3 = 0.f;
#pragma unroll
    for (int c = 0; c < Cn; c++) {
        n0 = fmaf(v[c].x, v[c].x, n0); n1 = fmaf(v[c].y, v[c].y, n1);
        n2 = fmaf(v[c].z, v[c].z, n2); n3 = fmaf(v[c].w, v[c].w, n3);
    }
    const float i0 = rsqrtf(fmaxf(n0, 1e-24f));
    const float i1 = rsqrtf(fmaxf(n1, 1e-24f));
    const float i2 = rsqrtf(fmaxf(n2, 1e-24f));
    const float i3 = rsqrtf(fmaxf(n3, 1e-24f));

    float at[Cn], a0[Cn];
#pragma unroll
    for (int c = 0; c < Cn; c++) {
        const float f0 = v[c].x * i0, f1 = v[c].y * i1;
        const float f2 = v[c].z * i2, f3 = v[c].w * i3;
        at[c] = (f0 + f1) + (f2 + f3);
        a0[c] = (m0 * f0 + m1 * f1) + (m2 * f2 + m3 * f3);
    }

    // Block reduce 33 slots; write partials (no atomics).
    __shared__ float sred[THR / 32][33];
    const int lane = tid & 31, w = tid >> 5;
#pragma unroll
    for (int c = 0; c < Cn; c++) { at[c] = wred(at[c]); a0[c] = wred(a0[c]); }
    cnt = wred(cnt);
    if (lane == 0) {
#pragma unroll
        for (int c = 0; c < Cn; c++) { sred[w][c] = at[c]; sred[w][16 + c] = a0[c]; }
        sred[w][32] = cnt;
    }
    __syncthreads();
    if (tid < 33) {
        float s = 0.f;
#pragma unroll
        for (int ww = 0; ww < THR / 32; ww++) s += sred[ww][tid];
        if (tid < 32)      g_part[z][b][tid][tile] = s;
        else if (z == 0)   g_cnt[b][tile] = s;
    }
}

// ---------------------------------------------------------------------------
// Finalize (PDL secondary): waits on pass1, reduces tile partials -> dM.
// grid (Bn, 2), 256 threads.
// ---------------------------------------------------------------------------
__global__ void finalize_kernel() {
    cudaGridDependencySynchronize();

    const int b = blockIdx.x, z = blockIdx.y;
    const int tid = threadIdx.x;

    __shared__ float s[8][32];
    __shared__ float sc[8];
    __shared__ float red[32];
    __shared__ float scnt;
    __shared__ float smean[2][Cn];
    __shared__ float srn[2];

    {   // 256 threads = 32 slots x 8 groups of 16 tiles
        const int slot = tid & 31, g = tid >> 5;
        const float* base = &g_part[z][b][slot][0] + g * 16;
        float a = 0.f;
#pragma unroll
        for (int k = 0; k < 4; k++) {
            const float4 v = *(const float4*)(base + 4 * k);
            a += (v.x + v.y) + (v.z + v.w);
        }
        s[g][slot] = a;
    }
    if (tid < 8) {
        const float* cb = &g_cnt[b][0] + tid * 16;
        float a = 0.f;
#pragma unroll
        for (int k = 0; k < 4; k++) {
            const float4 v = *(const float4*)(cb + 4 * k);
            a += (v.x + v.y) + (v.z + v.w);
        }
        sc[tid] = a;
    }
    __syncthreads();
    if (tid < 32) {
        float a = 0.f;
#pragma unroll
        for (int g = 0; g < 8; g++) a += s[g][tid];
        red[tid] = a;
    } else if (tid == 32) {
        float a = 0.f;
#pragma unroll
        for (int g = 0; g < 8; g++) a += sc[g];
        scnt = a;
    }
    __syncthreads();
    if (tid < 2) {
        const int cls = tid;
        const float cnt0 = scnt;
        const float cnt  = cls ? ((float)HWn - cnt0) : cnt0;
        const float inv  = 1.0f / (cnt + 1e-6f);
        float nm2 = 0.f;
#pragma unroll
        for (int c = 0; c < Cn; c++) {
            const float tot = red[c], s0 = red[16 + c];
            const float sv  = cls ? (tot - s0) : s0;
            const float m   = sv * inv;
            smean[cls][c] = m;
            nm2 = fmaf(m, m, nm2);
        }
        srn[cls] = 1.0f / fmaxf(sqrtf(nm2), 1e-8f);
    }
    __syncthreads();
    if (tid < Cn) {
        g_dm[z][b][tid] = smean[0][tid] * srn[0] - smean[1][tid] * srn[1];
    }
}

// ---------------------------------------------------------------------------
// Pass 3 (PDL secondary): class codes from packed bytes (no target read, no
// dtype flag); interleaved S/T channel loop; MSE with last-block writeout.
// grid (T3, Bn); 4 px/thread, float4 loads.
// ---------------------------------------------------------------------------
__global__ void __launch_bounds__(THR, 8)
pass3_kernel(const float* __restrict__ S, const float* __restrict__ T,
             float* __restrict__ out) {
    cudaGridDependencySynchronize();

    const int tile = blockIdx.x, b = blockIdx.y;
    const int tid  = threadIdx.x;

    __shared__ float sdM[2][Cn];
    __shared__ unsigned int slast;
    if (tid < 32) {
        const int z = tid >> 4, c = tid & 15;
        sdM[z][c] = g_dm[z][b][c];
    }
    __syncthreads();

    const float* Sb = S + ((size_t)b << 20);
    const float* Tb = T + ((size_t)b << 20);

    const int p = tile * PPB + tid * 4;
    const unsigned int pack = g_cls[b][p >> 2];
    const float s0 = (pack & 0x000000FFu) ? 1.f : -1.f;
    const float s1 = (pack & 0x0000FF00u) ? 1.f : -1.f;
    const float s2 = (pack & 0x00FF0000u) ? 1.f : -1.f;
    const float s3 = (pack & 0xFF000000u) ? 1.f : -1.f;

    // Interleaved S/T channel loop: independent accumulator sets.
    float nS0 = 0.f, nS1 = 0.f, nS2 = 0.f, nS3 = 0.f;
    float dS0 = 0.f, dS1 = 0.f, dS2 = 0.f, dS3 = 0.f;
    float nT0 = 0.f, nT1 = 0.f, nT2 = 0.f, nT3 = 0.f;
    float dT0 = 0.f, dT1 = 0.f, dT2 = 0.f, dT3 = 0.f;
#pragma unroll
    for (int c = 0; c < Cn; c++) {
        const float4 vs = ldcs4(Sb + ((size_t)c << 16) + p);
        const float4 vt = ldcs4(Tb + ((size_t)c << 16) + p);
        const float mS = sdM[0][c], mT = sdM[1][c];
        nS0 = fmaf(vs.x, vs.x, nS0); nS1 = fmaf(vs.y, vs.y, nS1);
        nS2 = fmaf(vs.z, vs.z, nS2); nS3 = fmaf(vs.w, vs.w, nS3);
        dS0 = fmaf(vs.x, mS, dS0);   dS1 = fmaf(vs.y, mS, dS1);
        dS2 = fmaf(vs.z, mS, dS2);   dS3 = fmaf(vs.w, mS, dS3);
        nT0 = fmaf(vt.x, vt.x, nT0); nT1 = fmaf(vt.y, vt.y, nT1);
        nT2 = fmaf(vt.z, vt.z, nT2); nT3 = fmaf(vt.w, vt.w, nT3);
        dT0 = fmaf(vt.x, mT, dT0);   dT1 = fmaf(vt.y, mT, dT1);
        dT2 = fmaf(vt.z, mT, dT2);   dT3 = fmaf(vt.w, mT, dT3);
    }

    const float e0 = __expf(s0 * dS0 * rsqrtf(fmaxf(nS0, 1e-24f)))
                   - __expf(s0 * dT0 * rsqrtf(fmaxf(nT0, 1e-24f)));
    const float e1 = __expf(s1 * dS1 * rsqrtf(fmaxf(nS1, 1e-24f)))
                   - __expf(s1 * dT1 * rsqrtf(fmaxf(nT1, 1e-24f)));
    const float e2 = __expf(s2 * dS2 * rsqrtf(fmaxf(nS2, 1e-24f)))
                   - __expf(s2 * dT2 * rsqrtf(fmaxf(nT2, 1e-24f)));
    const float e3 = __expf(s3 * dS3 * rsqrtf(fmaxf(nS3, 1e-24f)))
                   - __expf(s3 * dT3 * rsqrtf(fmaxf(nT3, 1e-24f)));
    float acc = fmaf(e0, e0, e1 * e1) + fmaf(e2, e2, e3 * e3);

    // Block reduce MSE partial, then last-block final reduction.
    __shared__ float smse[THR / 32];
    acc = wred(acc);
    const int lane = tid & 31, w = tid >> 5;
    if (lane == 0) smse[w] = acc;
    __syncthreads();
    const int gid = b * T3 + tile;
    if (tid == 0) {
        float sv = 0.f;
#pragma unroll
        for (int ww = 0; ww < THR / 32; ww++) sv += smse[ww];
        g_msep[gid] = sv;
        __threadfence();
        const unsigned int old = atomicAdd(&g_done, 1u);
        slast = (old == (unsigned int)(Bn * T3 - 1)) ? 1u : 0u;
    }
    __syncthreads();

    if (slast) {
        volatile float* mp = &g_msep[0];
        double d = 0.0;
#pragma unroll
        for (int k = 0; k < (Bn * T3) / THR; k++)
            d += (double)mp[tid * ((Bn * T3) / THR) + k];
        d = wredd(d);
        __shared__ double sd[THR / 32];
        if (lane == 0) sd[w] = d;
        __syncthreads();
        if (tid == 0) {
            double tot = 0.0;
#pragma unroll
            for (int ww = 0; ww < THR / 32; ww++) tot += sd[ww];
            out[0] = (float)(tot * (1.0 / ((double)Bn * (double)HWn)));
            g_done = 0;   // reset for next graph replay
        }
    }
}

extern "C" void kernel_launch(void* const* d_in, const int* in_sizes, int n_in,
                              void* d_out, int out_size) {
    const float* S  = (const float*)d_in[0];
    const float* T  = (const float*)d_in[1];
    const int*   TW = (const int*)d_in[2];
    float* out = (float*)d_out;

    // pass1: normal launch.
    dim3 g1(T1, Bn, 2);
    pass1_kernel<<<g1, THR>>>(S, T, TW);

    // finalize + pass3: programmatic dependent launches.
    cudaLaunchAttribute attr[1];
    attr[0].id = cudaLaunchAttributeProgrammaticStreamSerialization;
    attr[0].val.programmaticStreamSerializationAllowed = 1;

    {
        cudaLaunchConfig_t cfg = {};
        cfg.gridDim = dim3(Bn, 2);
        cfg.blockDim = dim3(256);
        cfg.attrs = attr;
        cfg.numAttrs = 1;
        cudaLaunchKernelEx(&cfg, finalize_kernel);
    }
    {
        cudaLaunchConfig_t cfg = {};
        cfg.gridDim = dim3(T3, Bn);
        cfg.blockDim = dim3(THR);
        cfg.attrs = attr;
        cfg.numAttrs = 1;
        cudaLaunchKernelEx(&cfg, pass3_kernel, S, T, out);
    }
}

// round 14
// speedup vs baseline: 1.0216x; 1.0213x over previous
#include <cuda_runtime.h>
#include <math.h>

// Problem constants
#define Bn   32
#define Cn   16
#define HWn  65536
#define T1   128               // tiles per batch, pass1 (512 px/tile)
#define T3   128               // tiles per batch, pass3 (512 px/tile)
#define PPB  512               // pixels per block
#define THR  128               // threads per block; 4 px/thread, float4

// Scratch (__device__ globals; fully overwritten each run)
__device__ float g_part[2][Bn][32][T1];   // [tensor][batch][slot:0-15 tot,16-31 cls0][tile]
__device__ float g_cnt[Bn][T1];           // class-0 count partials (z==0)
__device__ float g_dm[2][Bn][Cn];         // normalized mean difference vectors
__device__ float g_msep[Bn * T3];         // per-block MSE partials
__device__ int   g_is32;                  // target dtype flag (written by pass1)
__device__ unsigned int g_done;           // last-block counter (self-resetting)

__device__ __forceinline__ float wred(float v) {
    v += __shfl_down_sync(0xFFFFFFFFu, v, 16);
    v += __shfl_down_sync(0xFFFFFFFFu, v, 8);
    v += __shfl_down_sync(0xFFFFFFFFu, v, 4);
    v += __shfl_down_sync(0xFFFFFFFFu, v, 2);
    v += __shfl_down_sync(0xFFFFFFFFu, v, 1);
    return v;
}
__device__ __forceinline__ double wredd(double v) {
    v += __shfl_down_sync(0xFFFFFFFFu, v, 16);
    v += __shfl_down_sync(0xFFFFFFFFu, v, 8);
    v += __shfl_down_sync(0xFFFFFFFFu, v, 4);
    v += __shfl_down_sync(0xFFFFFFFFu, v, 2);
    v += __shfl_down_sync(0xFFFFFFFFu, v, 1);
    return v;
}
__device__ __forceinline__ float4 ldcs4(const float* p) {
    return __ldcs((const float4*)p);
}

// Per-block dtype sniff (pass1 only): int64 targets with values in {0,1} have
// all odd 32-bit words zero; int32 targets have random labels there. All
// blocks read the same 512 words (L2-broadcast) -> identical result.
__device__ __forceinline__ int sniff_is32(const int* __restrict__ tw, int tid) {
    int any = 0;
#pragma unroll
    for (int i = tid; i < 512; i += THR) any |= tw[2 * i + 1];
    return __syncthreads_or(any);
}

__device__ __forceinline__ void load_cls4(const int* __restrict__ twb, int p, int is32,
                                          int& c0, int& c1, int& c2, int& c3) {
    if (is32) {
        int4 v = __ldg((const int4*)(twb + p));
        c0 = v.x; c1 = v.y; c2 = v.z; c3 = v.w;
    } else {
        int4 a = __ldg((const int4*)(twb + 2 * p));
        int4 b = __ldg((const int4*)(twb + 2 * p + 4));
        c0 = a.x; c1 = a.z; c2 = b.x; c3 = b.z;
    }
}

// ---------------------------------------------------------------------------
// Pass 1 (proven-best shape): partial sums of L2-normalized features.
// grid (T1, Bn, 2); 4 px/thread, float4, 1 iteration. Hot loop untouched.
// ---------------------------------------------------------------------------
__global__ void __launch_bounds__(THR, 4)
pass1_kernel(const float* __restrict__ S, const float* __restrict__ T,
             const int* __restrict__ TW) {
    const int tile = blockIdx.x, b = blockIdx.y, z = blockIdx.z;
    const int tid  = threadIdx.x;
    const int is32 = sniff_is32(TW, tid);
    if (tid == 0) g_is32 = is32;   // same value from every block (benign race)

    const float* Xb  = (z ? T : S) + ((size_t)b << 20);
    const int*   twb = TW + (is32 ? ((size_t)b << 16) : ((size_t)b << 17));

    const int p = tile * PPB + tid * 4;
    int c0, c1, c2, c3;
    load_cls4(twb, p, is32, c0, c1, c2, c3);
    const float m0 = (c0 == 0) ? 1.f : 0.f;
    const float m1 = (c1 == 0) ? 1.f : 0.f;
    const float m2 = (c2 == 0) ? 1.f : 0.f;
    const float m3 = (c3 == 0) ? 1.f : 0.f;
    float cnt = (m0 + m1) + (m2 + m3);

    float4 v[Cn];
#pragma unroll
    for (int c = 0; c < Cn; c++) v[c] = ldcs4(Xb + ((size_t)c << 16) + p);

    float n0 = 0.f, n1 = 0.f, n2 = 0.f, n3 = 0.f;
#pragma unroll
    for (int c = 0; c < Cn; c++) {
        n0 = fmaf(v[c].x, v[c].x, n0); n1 = fmaf(v[c].y, v[c].y, n1);
        n2 = fmaf(v[c].z, v[c].z, n2); n3 = fmaf(v[c].w, v[c].w, n3);
    }
    const float i0 = rsqrtf(fmaxf(n0, 1e-24f));
    const float i1 = rsqrtf(fmaxf(n1, 1e-24f));
    const float i2 = rsqrtf(fmaxf(n2, 1e-24f));
    const float i3 = rsqrtf(fmaxf(n3, 1e-24f));

    float at[Cn], a0[Cn];
#pragma unroll
    for (int c = 0; c < Cn; c++) {
        const float f0 = v[c].x * i0, f1 = v[c].y * i1;
        const float f2 = v[c].z * i2, f3 = v[c].w * i3;
        at[c] = (f0 + f1) + (f2 + f3);
        a0[c] = (m0 * f0 + m1 * f1) + (m2 * f2 + m3 * f3);
    }

    // Block reduce 33 slots; write partials (no atomics).
    __shared__ float sred[THR / 32][33];
    const int lane = tid & 31, w = tid >> 5;
#pragma unroll
    for (int c = 0; c < Cn; c++) { at[c] = wred(at[c]); a0[c] = wred(a0[c]); }
    cnt = wred(cnt);
    if (lane == 0) {
#pragma unroll
        for (int c = 0; c < Cn; c++) { sred[w][c] = at[c]; sred[w][16 + c] = a0[c]; }
        sred[w][32] = cnt;
    }
    __syncthreads();
    if (tid < 33) {
        float s = 0.f;
#pragma unroll
        for (int ww = 0; ww < THR / 32; ww++) s += sred[ww][tid];
        if (tid < 32)      g_part[z][b][tid][tile] = s;
        else if (z == 0)   g_cnt[b][tile] = s;
    }
}

// ---------------------------------------------------------------------------
// Finalize (PDL secondary): waits on pass1, reduces tile partials -> dM.
// grid (Bn, 2), 256 threads.
// ---------------------------------------------------------------------------
__global__ void finalize_kernel() {
    // PDL: block until the upstream (pass1) grid's writes are visible.
    cudaGridDependencySynchronize();

    const int b = blockIdx.x, z = blockIdx.y;
    const int tid = threadIdx.x;

    __shared__ float s[8][32];
    __shared__ float sc[8];
    __shared__ float red[32];
    __shared__ float scnt;
    __shared__ float smean[2][Cn];
    __shared__ float srn[2];

    {   // 256 threads = 32 slots x 8 groups of 16 tiles
        const int slot = tid & 31, g = tid >> 5;
        const float* base = &g_part[z][b][slot][0] + g * 16;
        float a = 0.f;
#pragma unroll
        for (int k = 0; k < 4; k++) {
            const float4 v = *(const float4*)(base + 4 * k);
            a += (v.x + v.y) + (v.z + v.w);
        }
        s[g][slot] = a;
    }
    if (tid < 8) {
        const float* cb = &g_cnt[b][0] + tid * 16;
        float a = 0.f;
#pragma unroll
        for (int k = 0; k < 4; k++) {
            const float4 v = *(const float4*)(cb + 4 * k);
            a += (v.x + v.y) + (v.z + v.w);
        }
        sc[tid] = a;
    }
    __syncthreads();
    if (tid < 32) {
        float a = 0.f;
#pragma unroll
        for (int g = 0; g < 8; g++) a += s[g][tid];
        red[tid] = a;
    } else if (tid == 32) {
        float a = 0.f;
#pragma unroll
        for (int g = 0; g < 8; g++) a += sc[g];
        scnt = a;
    }
    __syncthreads();
    if (tid < 2) {
        const int cls = tid;
        const float cnt0 = scnt;
        const float cnt  = cls ? ((float)HWn - cnt0) : cnt0;
        const float inv  = 1.0f / (cnt + 1e-6f);
        float nm2 = 0.f;
#pragma unroll
        for (int c = 0; c < Cn; c++) {
            const float tot = red[c], s0 = red[16 + c];
            const float sv  = cls ? (tot - s0) : s0;
            const float m   = sv * inv;
            smean[cls][c] = m;
            nm2 = fmaf(m, m, nm2);
        }
        srn[cls] = 1.0f / fmaxf(sqrtf(nm2), 1e-8f);
    }
    __syncthreads();
    if (tid < Cn) {
        g_dm[z][b][tid] = smean[0][tid] * srn[0] - smean[1][tid] * srn[1];
    }
}

// ---------------------------------------------------------------------------
// Pass 3 (PDL secondary): interleaved S/T channel loop (32 outstanding
// LDG.128/thread); cd = dot(v,dM)*rsqrt(||v||^2); pcsim = exp(+-cd); MSE.
// grid (T3, Bn); 4 px/thread, float4 loads.
// ---------------------------------------------------------------------------
__global__ void __launch_bounds__(THR, 8)
pass3_kernel(const float* __restrict__ S, const float* __restrict__ T,
             const int* __restrict__ TW, float* __restrict__ out) {
    // PDL: block until the upstream (finalize) grid's writes are visible.
    cudaGridDependencySynchronize();

    const int tile = blockIdx.x, b = blockIdx.y;
    const int tid  = threadIdx.x;

    __shared__ float sdM[2][Cn];
    __shared__ int sis32;
    __shared__ unsigned int slast;
    if (tid < 32) {
        const int z = tid >> 4, c = tid & 15;
        sdM[z][c] = g_dm[z][b][c];
    } else if (tid == 32) {
        sis32 = g_is32;
    }
    __syncthreads();
    const int is32 = sis32;

    const float* Sb  = S + ((size_t)b << 20);
    const float* Tb  = T + ((size_t)b << 20);
    const int*   twb = TW + (is32 ? ((size_t)b << 16) : ((size_t)b << 17));

    const int p = tile * PPB + tid * 4;
    int c0, c1, c2, c3;
    load_cls4(twb, p, is32, c0, c1, c2, c3);
    const float s0 = (c0 == 0) ? 1.f : -1.f;
    const float s1 = (c1 == 0) ? 1.f : -1.f;
    const float s2 = (c2 == 0) ? 1.f : -1.f;
    const float s3 = (c3 == 0) ? 1.f : -1.f;

    // Interleaved S/T channel loop: independent accumulator sets.
    float nS0 = 0.f, nS1 = 0.f, nS2 = 0.f, nS3 = 0.f;
    float dS0 = 0.f, dS1 = 0.f, dS2 = 0.f, dS3 = 0.f;
    float nT0 = 0.f, nT1 = 0.f, nT2 = 0.f, nT3 = 0.f;
    float dT0 = 0.f, dT1 = 0.f, dT2 = 0.f, dT3 = 0.f;
#pragma unroll
    for (int c = 0; c < Cn; c++) {
        const float4 vs = ldcs4(Sb + ((size_t)c << 16) + p);
        const float4 vt = ldcs4(Tb + ((size_t)c << 16) + p);
        const float mS = sdM[0][c], mT = sdM[1][c];
        nS0 = fmaf(vs.x, vs.x, nS0); nS1 = fmaf(vs.y, vs.y, nS1);
        nS2 = fmaf(vs.z, vs.z, nS2); nS3 = fmaf(vs.w, vs.w, nS3);
        dS0 = fmaf(vs.x, mS, dS0);   dS1 = fmaf(vs.y, mS, dS1);
        dS2 = fmaf(vs.z, mS, dS2);   dS3 = fmaf(vs.w, mS, dS3);
        nT0 = fmaf(vt.x, vt.x, nT0); nT1 = fmaf(vt.y, vt.y, nT1);
        nT2 = fmaf(vt.z, vt.z, nT2); nT3 = fmaf(vt.w, vt.w, nT3);
        dT0 = fmaf(vt.x, mT, dT0);   dT1 = fmaf(vt.y, mT, dT1);
        dT2 = fmaf(vt.z, mT, dT2);   dT3 = fmaf(vt.w, mT, dT3);
    }

    const float e0 = __expf(s0 * dS0 * rsqrtf(fmaxf(nS0, 1e-24f)))
                   - __expf(s0 * dT0 * rsqrtf(fmaxf(nT0, 1e-24f)));
    const float e1 = __expf(s1 * dS1 * rsqrtf(fmaxf(nS1, 1e-24f)))
                   - __expf(s1 * dT1 * rsqrtf(fmaxf(nT1, 1e-24f)));
    const float e2 = __expf(s2 * dS2 * rsqrtf(fmaxf(nS2, 1e-24f)))
                   - __expf(s2 * dT2 * rsqrtf(fmaxf(nT2, 1e-24f)));
    const float e3 = __expf(s3 * dS3 * rsqrtf(fmaxf(nS3, 1e-24f)))
                   - __expf(s3 * dT3 * rsqrtf(fmaxf(nT3, 1e-24f)));
    float acc = fmaf(e0, e0, e1 * e1) + fmaf(e2, e2, e3 * e3);

    // Block reduce MSE partial, then last-block final reduction.
    __shared__ float smse[THR / 32];
    acc = wred(acc);
    const int lane = tid & 31, w = tid >> 5;
    if (lane == 0) smse[w] = acc;
    __syncthreads();
    const int gid = b * T3 + tile;
    if (tid == 0) {
        float sv = 0.f;
#pragma unroll
        for (int ww = 0; ww < THR / 32; ww++) sv += smse[ww];
        g_msep[gid] = sv;
        __threadfence();
        const unsigned int old = atomicAdd(&g_done, 1u);
        slast = (old == (unsigned int)(Bn * T3 - 1)) ? 1u : 0u;
    }
    __syncthreads();

    if (slast) {
        volatile float* mp = &g_msep[0];
        double d = 0.0;
#pragma unroll
        for (int k = 0; k < (Bn * T3) / THR; k++)
            d += (double)mp[tid * ((Bn * T3) / THR) + k];
        d = wredd(d);
        __shared__ double sd[THR / 32];
        if (lane == 0) sd[w] = d;
        __syncthreads();
        if (tid == 0) {
            double tot = 0.0;
#pragma unroll
            for (int ww = 0; ww < THR / 32; ww++) tot += sd[ww];
            out[0] = (float)(tot * (1.0 / ((double)Bn * (double)HWn)));
            g_done = 0;   // reset for next graph replay
        }
    }
}

extern "C" void kernel_launch(void* const* d_in, const int* in_sizes, int n_in,
                              void* d_out, int out_size) {
    const float* S  = (const float*)d_in[0];
    const float* T  = (const float*)d_in[1];
    const int*   TW = (const int*)d_in[2];
    float* out = (float*)d_out;

    // pass1: normal launch.
    dim3 g1(T1, Bn, 2);
    pass1_kernel<<<g1, THR>>>(S, T, TW);

    // finalize + pass3: programmatic dependent launches (overlap launch
    // latency and the tiny finalize with the big kernels' tails).
    cudaLaunchAttribute attr[1];
    attr[0].id = cudaLaunchAttributeProgrammaticStreamSerialization;
    attr[0].val.programmaticStreamSerializationAllowed = 1;

    {
        cudaLaunchConfig_t cfg = {};
        cfg.gridDim = dim3(Bn, 2);
        cfg.blockDim = dim3(256);
        cfg.attrs = attr;
        cfg.numAttrs = 1;
        cudaLaunchKernelEx(&cfg, finalize_kernel);
    }
    {
        cudaLaunchConfig_t cfg = {};
        cfg.gridDim = dim3(T3, Bn);
        cfg.blockDim = dim3(THR);
        cfg.attrs = attr;
        cfg.numAttrs = 1;
        cudaLaunchKernelEx(&cfg, pass3_kernel, S, T, TW, out);
    }
}

// round 15
// speedup vs baseline: 1.0236x; 1.0020x over previous
#include <cuda_runtime.h>
#include <math.h>

// Problem constants
#define Bn   32
#define Cn   16
#define HWn  65536
#define T1   128               // tiles per batch, pass1 (512 px/tile)
#define T3   128               // tiles per batch, pass3 (512 px/tile)
#define PPB  512               // pixels per block
#define THR  128               // threads per block; 4 px/thread, float4

// Scratch (__device__ globals; fully overwritten each run)
__device__ float g_part[2][Bn][32][T1];   // [tensor][batch][slot:0-15 tot,16-31 cls0][tile]
__device__ float g_cnt[Bn][T1];           // class-0 count partials (z==0)
__device__ float g_dm[2][Bn][Cn];         // normalized mean difference vectors
__device__ float g_msep[Bn * T3];         // per-block MSE partials
__device__ int   g_is32;                  // target dtype flag (written by pass1)
__device__ unsigned int g_done;           // last-block counter (self-resetting)

__device__ __forceinline__ float wred(float v) {
    v += __shfl_down_sync(0xFFFFFFFFu, v, 16);
    v += __shfl_down_sync(0xFFFFFFFFu, v, 8);
    v += __shfl_down_sync(0xFFFFFFFFu, v, 4);
    v += __shfl_down_sync(0xFFFFFFFFu, v, 2);
    v += __shfl_down_sync(0xFFFFFFFFu, v, 1);
    return v;
}
__device__ __forceinline__ double wredd(double v) {
    v += __shfl_down_sync(0xFFFFFFFFu, v, 16);
    v += __shfl_down_sync(0xFFFFFFFFu, v, 8);
    v += __shfl_down_sync(0xFFFFFFFFu, v, 4);
    v += __shfl_down_sync(0xFFFFFFFFu, v, 2);
    v += __shfl_down_sync(0xFFFFFFFFu, v, 1);
    return v;
}
__device__ __forceinline__ float4 ldcs4(const float* p) {
    return __ldcs((const float4*)p);
}

// Per-block dtype sniff (pass1 only): int64 targets with values in {0,1} have
// all odd 32-bit words zero; int32 targets have random labels there (P(all
// 128 words zero) = 2^-128). All blocks read the same words (L2-broadcast).
__device__ __forceinline__ int sniff_is32(const int* __restrict__ tw, int tid) {
    int any = 0;
    if (tid < 128) any = tw[2 * tid + 1];
    return __syncthreads_or(any);
}

__device__ __forceinline__ void load_cls4(const int* __restrict__ twb, int p, int is32,
                                          int& c0, int& c1, int& c2, int& c3) {
    if (is32) {
        int4 v = __ldg((const int4*)(twb + p));
        c0 = v.x; c1 = v.y; c2 = v.z; c3 = v.w;
    } else {
        int4 a = __ldg((const int4*)(twb + 2 * p));
        int4 b = __ldg((const int4*)(twb + 2 * p + 4));
        c0 = a.x; c1 = a.z; c2 = b.x; c3 = b.z;
    }
}

// ---------------------------------------------------------------------------
// Pass 1: partial sums of L2-normalized features. grid (T1, Bn, 2);
// 4 px/thread, float4, 1 iteration; 5 blocks/SM (20 warps).
// ---------------------------------------------------------------------------
__global__ void __launch_bounds__(THR, 5)
pass1_kernel(const float* __restrict__ S, const float* __restrict__ T,
             const int* __restrict__ TW) {
    const int tile = blockIdx.x, b = blockIdx.y, z = blockIdx.z;
    const int tid  = threadIdx.x;
    const int is32 = sniff_is32(TW, tid);
    if (tid == 0) g_is32 = is32;   // same value from every block (benign race)

    const float* Xb  = (z ? T : S) + ((size_t)b << 20);
    const int*   twb = TW + (is32 ? ((size_t)b << 16) : ((size_t)b << 17));

    const int p = tile * PPB + tid * 4;
    int c0, c1, c2, c3;
    load_cls4(twb, p, is32, c0, c1, c2, c3);
    const float m0 = (c0 == 0) ? 1.f : 0.f;
    const float m1 = (c1 == 0) ? 1.f : 0.f;
    const float m2 = (c2 == 0) ? 1.f : 0.f;
    const float m3 = (c3 == 0) ? 1.f : 0.f;
    float cnt = (m0 + m1) + (m2 + m3);

    float4 v[Cn];
#pragma unroll
    for (int c = 0; c < Cn; c++) v[c] = ldcs4(Xb + ((size_t)c << 16) + p);

    float n0 = 0.f, n1 = 0.f, n2 = 0.f, n3 = 0.f;
#pragma unroll
    for (int c = 0; c < Cn; c++) {
        n0 = fmaf(v[c].x, v[c].x, n0); n1 = fmaf(v[c].y, v[c].y, n1);
        n2 = fmaf(v[c].z, v[c].z, n2); n3 = fmaf(v[c].w, v[c].w, n3);
    }
    const float i0 = rsqrtf(fmaxf(n0, 1e-24f));
    const float i1 = rsqrtf(fmaxf(n1, 1e-24f));
    const float i2 = rsqrtf(fmaxf(n2, 1e-24f));
    const float i3 = rsqrtf(fmaxf(n3, 1e-24f));

    float at[Cn], a0[Cn];
#pragma unroll
    for (int c = 0; c < Cn; c++) {
        const float f0 = v[c].x * i0, f1 = v[c].y * i1;
        const float f2 = v[c].z * i2, f3 = v[c].w * i3;
        at[c] = (f0 + f1) + (f2 + f3);
        a0[c] = (m0 * f0 + m1 * f1) + (m2 * f2 + m3 * f3);
    }

    // Block reduce 33 slots; write partials (no atomics).
    __shared__ float sred[THR / 32][33];
    const int lane = tid & 31, w = tid >> 5;
#pragma unroll
    for (int c = 0; c < Cn; c++) { at[c] = wred(at[c]); a0[c] = wred(a0[c]); }
    cnt = wred(cnt);
    if (lane == 0) {
#pragma unroll
        for (int c = 0; c < Cn; c++) { sred[w][c] = at[c]; sred[w][16 + c] = a0[c]; }
        sred[w][32] = cnt;
    }
    __syncthreads();
    if (tid < 33) {
        float s = 0.f;
#pragma unroll
        for (int ww = 0; ww < THR / 32; ww++) s += sred[ww][tid];
        if (tid < 32)      g_part[z][b][tid][tile] = s;
        else if (z == 0)   g_cnt[b][tile] = s;
    }
}

// ---------------------------------------------------------------------------
// Finalize (PDL secondary): waits on pass1, reduces tile partials -> dM.
// grid (Bn, 2), 256 threads.
// ---------------------------------------------------------------------------
__global__ void finalize_kernel() {
    cudaGridDependencySynchronize();

    const int b = blockIdx.x, z = blockIdx.y;
    const int tid = threadIdx.x;

    __shared__ float s[8][32];
    __shared__ float sc[8];
    __shared__ float red[32];
    __shared__ float scnt;
    __shared__ float smean[2][Cn];
    __shared__ float srn[2];

    {   // 256 threads = 32 slots x 8 groups of 16 tiles
        const int slot = tid & 31, g = tid >> 5;
        const float* base = &g_part[z][b][slot][0] + g * 16;
        float a = 0.f;
#pragma unroll
        for (int k = 0; k < 4; k++) {
            const float4 v = *(const float4*)(base + 4 * k);
            a += (v.x + v.y) + (v.z + v.w);
        }
        s[g][slot] = a;
    }
    if (tid < 8) {
        const float* cb = &g_cnt[b][0] + tid * 16;
        float a = 0.f;
#pragma unroll
        for (int k = 0; k < 4; k++) {
            const float4 v = *(const float4*)(cb + 4 * k);
            a += (v.x + v.y) + (v.z + v.w);
        }
        sc[tid] = a;
    }
    __syncthreads();
    if (tid < 32) {
        float a = 0.f;
#pragma unroll
        for (int g = 0; g < 8; g++) a += s[g][tid];
        red[tid] = a;
    } else if (tid == 32) {
        float a = 0.f;
#pragma unroll
        for (int g = 0; g < 8; g++) a += sc[g];
        scnt = a;
    }
    __syncthreads();
    if (tid < 2) {
        const int cls = tid;
        const float cnt0 = scnt;
        const float cnt  = cls ? ((float)HWn - cnt0) : cnt0;
        const float inv  = 1.0f / (cnt + 1e-6f);
        float nm2 = 0.f;
#pragma unroll
        for (int c = 0; c < Cn; c++) {
            const float tot = red[c], s0 = red[16 + c];
            const float sv  = cls ? (tot - s0) : s0;
            const float m   = sv * inv;
            smean[cls][c] = m;
            nm2 = fmaf(m, m, nm2);
        }
        srn[cls] = 1.0f / fmaxf(sqrtf(nm2), 1e-8f);
    }
    __syncthreads();
    if (tid < Cn) {
        g_dm[z][b][tid] = smean[0][tid] * srn[0] - smean[1][tid] * srn[1];
    }
}

// ---------------------------------------------------------------------------
// Pass 3 (PDL secondary): interleaved S/T channel loop (32 outstanding
// LDG.128/thread); cd = dot(v,dM)*rsqrt(||v||^2); pcsim = exp(+-cd); MSE.
// grid (T3, Bn); 4 px/thread, float4 loads.
// ---------------------------------------------------------------------------
__global__ void __launch_bounds__(THR, 8)
pass3_kernel(const float* __restrict__ S, const float* __restrict__ T,
             const int* __restrict__ TW, float* __restrict__ out) {
    cudaGridDependencySynchronize();

    const int tile = blockIdx.x, b = blockIdx.y;
    const int tid  = threadIdx.x;

    __shared__ float sdM[2][Cn];
    __shared__ int sis32;
    __shared__ unsigned int slast;
    if (tid < 32) {
        const int z = tid >> 4, c = tid & 15;
        sdM[z][c] = g_dm[z][b][c];
    } else if (tid == 32) {
        sis32 = g_is32;
    }
    __syncthreads();
    const int is32 = sis32;

    const float* Sb  = S + ((size_t)b << 20);
    const float* Tb  = T + ((size_t)b << 20);
    const int*   twb = TW + (is32 ? ((size_t)b << 16) : ((size_t)b << 17));

    const int p = tile * PPB + tid * 4;
    int c0, c1, c2, c3;
    load_cls4(twb, p, is32, c0, c1, c2, c3);
    const float s0 = (c0 == 0) ? 1.f : -1.f;
    const float s1 = (c1 == 0) ? 1.f : -1.f;
    const float s2 = (c2 == 0) ? 1.f : -1.f;
    const float s3 = (c3 == 0) ? 1.f : -1.f;

    // Interleaved S/T channel loop: independent accumulator sets.
    float nS0 = 0.f, nS1 = 0.f, nS2 = 0.f, nS3 = 0.f;
    float dS0 = 0.f, dS1 = 0.f, dS2 = 0.f, dS3 = 0.f;
    float nT0 = 0.f, nT1 = 0.f, nT2 = 0.f, nT3 = 0.f;
    float dT0 = 0.f, dT1 = 0.f, dT2 = 0.f, dT3 = 0.f;
#pragma unroll
    for (int c = 0; c < Cn; c++) {
        const float4 vs = ldcs4(Sb + ((size_t)c << 16) + p);
        const float4 vt = ldcs4(Tb + ((size_t)c << 16) + p);
        const float mS = sdM[0][c], mT = sdM[1][c];
        nS0 = fmaf(vs.x, vs.x, nS0); nS1 = fmaf(vs.y, vs.y, nS1);
        nS2 = fmaf(vs.z, vs.z, nS2); nS3 = fmaf(vs.w, vs.w, nS3);
        dS0 = fmaf(vs.x, mS, dS0);   dS1 = fmaf(vs.y, mS, dS1);
        dS2 = fmaf(vs.z, mS, dS2);   dS3 = fmaf(vs.w, mS, dS3);
        nT0 = fmaf(vt.x, vt.x, nT0); nT1 = fmaf(vt.y, vt.y, nT1);
        nT2 = fmaf(vt.z, vt.z, nT2); nT3 = fmaf(vt.w, vt.w, nT3);
        dT0 = fmaf(vt.x, mT, dT0);   dT1 = fmaf(vt.y, mT, dT1);
        dT2 = fmaf(vt.z, mT, dT2);   dT3 = fmaf(vt.w, mT, dT3);
    }

    const float e0 = __expf(s0 * dS0 * rsqrtf(fmaxf(nS0, 1e-24f)))
                   - __expf(s0 * dT0 * rsqrtf(fmaxf(nT0, 1e-24f)));
    const float e1 = __expf(s1 * dS1 * rsqrtf(fmaxf(nS1, 1e-24f)))
                   - __expf(s1 * dT1 * rsqrtf(fmaxf(nT1, 1e-24f)));
    const float e2 = __expf(s2 * dS2 * rsqrtf(fmaxf(nS2, 1e-24f)))
                   - __expf(s2 * dT2 * rsqrtf(fmaxf(nT2, 1e-24f)));
    const float e3 = __expf(s3 * dS3 * rsqrtf(fmaxf(nS3, 1e-24f)))
                   - __expf(s3 * dT3 * rsqrtf(fmaxf(nT3, 1e-24f)));
    float acc = fmaf(e0, e0, e1 * e1) + fmaf(e2, e2, e3 * e3);

    // Block reduce MSE partial, then last-block final reduction.
    __shared__ float smse[THR / 32];
    acc = wred(acc);
    const int lane = tid & 31, w = tid >> 5;
    if (lane == 0) smse[w] = acc;
    __syncthreads();
    const int gid = b * T3 + tile;
    if (tid == 0) {
        float sv = 0.f;
#pragma unroll
        for (int ww = 0; ww < THR / 32; ww++) sv += smse[ww];
        g_msep[gid] = sv;
        __threadfence();
        const unsigned int old = atomicAdd(&g_done, 1u);
        slast = (old == (unsigned int)(Bn * T3 - 1)) ? 1u : 0u;
    }
    __syncthreads();

    if (slast) {
        volatile float* mp = &g_msep[0];
        double d = 0.0;
#pragma unroll
        for (int k = 0; k < (Bn * T3) / THR; k++)
            d += (double)mp[tid * ((Bn * T3) / THR) + k];
        d = wredd(d);
        __shared__ double sd[THR / 32];
        if (lane == 0) sd[w] = d;
        __syncthreads();
        if (tid == 0) {
            double tot = 0.0;
#pragma unroll
            for (int ww = 0; ww < THR / 32; ww++) tot += sd[ww];
            out[0] = (float)(tot * (1.0 / ((double)Bn * (double)HWn)));
            g_done = 0;   // reset for next graph replay
        }
    }
}

extern "C" void kernel_launch(void* const* d_in, const int* in_sizes, int n_in,
                              void* d_out, int out_size) {
    const float* S  = (const float*)d_in[0];
    const float* T  = (const float*)d_in[1];
    const int*   TW = (const int*)d_in[2];
    float* out = (float*)d_out;

    // pass1: normal launch.
    dim3 g1(T1, Bn, 2);
    pass1_kernel<<<g1, THR>>>(S, T, TW);

    // finalize + pass3: programmatic dependent launches.
    cudaLaunchAttribute attr[1];
    attr[0].id = cudaLaunchAttributeProgrammaticStreamSerialization;
    attr[0].val.programmaticStreamSerializationAllowed = 1;

    {
        cudaLaunchConfig_t cfg = {};
        cfg.gridDim = dim3(Bn, 2);
        cfg.blockDim = dim3(256);
        cfg.attrs = attr;
        cfg.numAttrs = 1;
        cudaLaunchKernelEx(&cfg, finalize_kernel);
    }
    {
        cudaLaunchConfig_t cfg = {};
        cfg.gridDim = dim3(T3, Bn);
        cfg.blockDim = dim3(THR);
        cfg.attrs = attr;
        cfg.numAttrs = 1;
        cudaLaunchKernelEx(&cfg, pass3_kernel, S, T, TW, out);
    }
}

// round 16
// speedup vs baseline: 1.0854x; 1.0604x over previous
#include <cuda_runtime.h>
#include <math.h>

// Problem constants
#define Bn   32
#define Cn   16
#define HWn  65536
#define T1   128               // tiles per batch, pass1 (512 px/tile)
#define T3   128               // tiles per batch, pass3 (512 px/tile)
#define PPB  512               // pixels per block
#define THR  128               // threads per block; 4 px/thread, float4

// Scratch (__device__ globals; fully overwritten each run)
__device__ float g_part[2][Bn][32][T1];   // [tensor][batch][slot:0-15 tot,16-31 cls0][tile]
__device__ float g_cnt[Bn][T1];           // class-0 count partials (z==0)
__device__ float g_dm[2][Bn][Cn];         // normalized mean difference vectors
__device__ float g_msep[Bn * T3];         // per-block MSE partials
__device__ int   g_is32;                  // target dtype flag (written by pass1)
__device__ unsigned int g_done;           // last-block counter (self-resetting)

__device__ __forceinline__ float wred(float v) {
    v += __shfl_down_sync(0xFFFFFFFFu, v, 16);
    v += __shfl_down_sync(0xFFFFFFFFu, v, 8);
    v += __shfl_down_sync(0xFFFFFFFFu, v, 4);
    v += __shfl_down_sync(0xFFFFFFFFu, v, 2);
    v += __shfl_down_sync(0xFFFFFFFFu, v, 1);
    return v;
}
__device__ __forceinline__ double wredd(double v) {
    v += __shfl_down_sync(0xFFFFFFFFu, v, 16);
    v += __shfl_down_sync(0xFFFFFFFFu, v, 8);
    v += __shfl_down_sync(0xFFFFFFFFu, v, 4);
    v += __shfl_down_sync(0xFFFFFFFFu, v, 2);
    v += __shfl_down_sync(0xFFFFFFFFu, v, 1);
    return v;
}
__device__ __forceinline__ float4 ldg4(const float* p) {
    return __ldg((const float4*)p);     // default caching: lands in L1
}
__device__ __forceinline__ float4 ldcs4(const float* p) {
    return __ldcs((const float4*)p);    // streaming (pass3 only; no re-read)
}

// Per-block dtype sniff (pass1 only): int64 targets with values in {0,1} have
// all odd 32-bit words zero; int32 targets have random labels there (P(all
// 128 words zero) = 2^-128). All blocks read the same words (L2-broadcast).
__device__ __forceinline__ int sniff_is32(const int* __restrict__ tw, int tid) {
    int any = 0;
    if (tid < 128) any = tw[2 * tid + 1];
    return __syncthreads_or(any);
}

__device__ __forceinline__ void load_cls4(const int* __restrict__ twb, int p, int is32,
                                          int& c0, int& c1, int& c2, int& c3) {
    if (is32) {
        int4 v = __ldg((const int4*)(twb + p));
        c0 = v.x; c1 = v.y; c2 = v.z; c3 = v.w;
    } else {
        int4 a = __ldg((const int4*)(twb + 2 * p));
        int4 b = __ldg((const int4*)(twb + 2 * p + 4));
        c0 = a.x; c1 = a.z; c2 = b.x; c3 = b.z;
    }
}

// ---------------------------------------------------------------------------
// Pass 1 (streaming, L1 re-read): loop 1 streams channels computing norms
// (no held tile), loop 2 re-loads from L1 and reduces each channel inline.
// grid (T1, Bn, 2); 4 px/thread, float4.
// ---------------------------------------------------------------------------
__global__ void __launch_bounds__(THR, 5)
pass1_kernel(const float* __restrict__ S, const float* __restrict__ T,
             const int* __restrict__ TW) {
    const int tile = blockIdx.x, b = blockIdx.y, z = blockIdx.z;
    const int tid  = threadIdx.x;
    const int lane = tid & 31, w = tid >> 5;
    const int is32 = sniff_is32(TW, tid);
    if (tid == 0) g_is32 = is32;   // same value from every block (benign race)

    const float* Xb  = (z ? T : S) + ((size_t)b << 20);
    const int*   twb = TW + (is32 ? ((size_t)b << 16) : ((size_t)b << 17));

    const int p = tile * PPB + tid * 4;
    int c0, c1, c2, c3;
    load_cls4(twb, p, is32, c0, c1, c2, c3);
    const float m0 = (c0 == 0) ? 1.f : 0.f;
    const float m1 = (c1 == 0) ? 1.f : 0.f;
    const float m2 = (c2 == 0) ? 1.f : 0.f;
    const float m3 = (c3 == 0) ? 1.f : 0.f;
    float cnt = (m0 + m1) + (m2 + m3);

    // Loop 1: streaming norm accumulation (caching loads -> L1 resident).
    float n0 = 0.f, n1 = 0.f, n2 = 0.f, n3 = 0.f;
#pragma unroll
    for (int c = 0; c < Cn; c++) {
        const float4 v = ldg4(Xb + ((size_t)c << 16) + p);
        n0 = fmaf(v.x, v.x, n0); n1 = fmaf(v.y, v.y, n1);
        n2 = fmaf(v.z, v.z, n2); n3 = fmaf(v.w, v.w, n3);
    }
    const float i0 = rsqrtf(fmaxf(n0, 1e-24f));
    const float i1 = rsqrtf(fmaxf(n1, 1e-24f));
    const float i2 = rsqrtf(fmaxf(n2, 1e-24f));
    const float i3 = rsqrtf(fmaxf(n3, 1e-24f));

    // Loop 2: re-read from L1, reduce each channel inline (no tile, no
    // monolithic epilogue; shuffles overlap next channel's L1-hit loads).
    __shared__ float sred[THR / 32][33];
#pragma unroll
    for (int c = 0; c < Cn; c++) {
        const float4 v = ldg4(Xb + ((size_t)c << 16) + p);
        const float f0 = v.x * i0, f1 = v.y * i1;
        const float f2 = v.z * i2, f3 = v.w * i3;
        float at = (f0 + f1) + (f2 + f3);
        float a0 = (m0 * f0 + m1 * f1) + (m2 * f2 + m3 * f3);
        at = wred(at); a0 = wred(a0);
        if (lane == 0) { sred[w][c] = at; sred[w][16 + c] = a0; }
    }
    cnt = wred(cnt);
    if (lane == 0) sred[w][32] = cnt;
    __syncthreads();
    if (tid < 33) {
        float s = 0.f;
#pragma unroll
        for (int ww = 0; ww < THR / 32; ww++) s += sred[ww][tid];
        if (tid < 32)      g_part[z][b][tid][tile] = s;
        else if (z == 0)   g_cnt[b][tile] = s;
    }
}

// ---------------------------------------------------------------------------
// Finalize (PDL secondary): waits on pass1, reduces tile partials -> dM.
// grid (Bn, 2), 256 threads.
// ---------------------------------------------------------------------------
__global__ void finalize_kernel() {
    cudaGridDependencySynchronize();

    const int b = blockIdx.x, z = blockIdx.y;
    const int tid = threadIdx.x;

    __shared__ float s[8][32];
    __shared__ float sc[8];
    __shared__ float red[32];
    __shared__ float scnt;
    __shared__ float smean[2][Cn];
    __shared__ float srn[2];

    {   // 256 threads = 32 slots x 8 groups of 16 tiles
        const int slot = tid & 31, g = tid >> 5;
        const float* base = &g_part[z][b][slot][0] + g * 16;
        float a = 0.f;
#pragma unroll
        for (int k = 0; k < 4; k++) {
            const float4 v = *(const float4*)(base + 4 * k);
            a += (v.x + v.y) + (v.z + v.w);
        }
        s[g][slot] = a;
    }
    if (tid < 8) {
        const float* cb = &g_cnt[b][0] + tid * 16;
        float a = 0.f;
#pragma unroll
        for (int k = 0; k < 4; k++) {
            const float4 v = *(const float4*)(cb + 4 * k);
            a += (v.x + v.y) + (v.z + v.w);
        }
        sc[tid] = a;
    }
    __syncthreads();
    if (tid < 32) {
        float a = 0.f;
#pragma unroll
        for (int g = 0; g < 8; g++) a += s[g][tid];
        red[tid] = a;
    } else if (tid == 32) {
        float a = 0.f;
#pragma unroll
        for (int g = 0; g < 8; g++) a += sc[g];
        scnt = a;
    }
    __syncthreads();
    if (tid < 2) {
        const int cls = tid;
        const float cnt0 = scnt;
        const float cnt  = cls ? ((float)HWn - cnt0) : cnt0;
        const float inv  = 1.0f / (cnt + 1e-6f);
        float nm2 = 0.f;
#pragma unroll
        for (int c = 0; c < Cn; c++) {
            const float tot = red[c], s0 = red[16 + c];
            const float sv  = cls ? (tot - s0) : s0;
            const float m   = sv * inv;
            smean[cls][c] = m;
            nm2 = fmaf(m, m, nm2);
        }
        srn[cls] = 1.0f / fmaxf(sqrtf(nm2), 1e-8f);
    }
    __syncthreads();
    if (tid < Cn) {
        g_dm[z][b][tid] = smean[0][tid] * srn[0] - smean[1][tid] * srn[1];
    }
}

// ---------------------------------------------------------------------------
// Pass 3 (PDL secondary): interleaved S/T channel loop (32 outstanding
// LDG.128/thread); cd = dot(v,dM)*rsqrt(||v||^2); pcsim = exp(+-cd); MSE.
// grid (T3, Bn); 4 px/thread, float4 loads. (Unchanged from R15.)
// ---------------------------------------------------------------------------
__global__ void __launch_bounds__(THR, 8)
pass3_kernel(const float* __restrict__ S, const float* __restrict__ T,
             const int* __restrict__ TW, float* __restrict__ out) {
    cudaGridDependencySynchronize();

    const int tile = blockIdx.x, b = blockIdx.y;
    const int tid  = threadIdx.x;

    __shared__ float sdM[2][Cn];
    __shared__ int sis32;
    __shared__ unsigned int slast;
    if (tid < 32) {
        const int z = tid >> 4, c = tid & 15;
        sdM[z][c] = g_dm[z][b][c];
    } else if (tid == 32) {
        sis32 = g_is32;
    }
    __syncthreads();
    const int is32 = sis32;

    const float* Sb  = S + ((size_t)b << 20);
    const float* Tb  = T + ((size_t)b << 20);
    const int*   twb = TW + (is32 ? ((size_t)b << 16) : ((size_t)b << 17));

    const int p = tile * PPB + tid * 4;
    int c0, c1, c2, c3;
    load_cls4(twb, p, is32, c0, c1, c2, c3);
    const float s0 = (c0 == 0) ? 1.f : -1.f;
    const float s1 = (c1 == 0) ? 1.f : -1.f;
    const float s2 = (c2 == 0) ? 1.f : -1.f;
    const float s3 = (c3 == 0) ? 1.f : -1.f;

    float nS0 = 0.f, nS1 = 0.f, nS2 = 0.f, nS3 = 0.f;
    float dS0 = 0.f, dS1 = 0.f, dS2 = 0.f, dS3 = 0.f;
    float nT0 = 0.f, nT1 = 0.f, nT2 = 0.f, nT3 = 0.f;
    float dT0 = 0.f, dT1 = 0.f, dT2 = 0.f, dT3 = 0.f;
#pragma unroll
    for (int c = 0; c < Cn; c++) {
        const float4 vs = ldcs4(Sb + ((size_t)c << 16) + p);
        const float4 vt = ldcs4(Tb + ((size_t)c << 16) + p);
        const float mS = sdM[0][c], mT = sdM[1][c];
        nS0 = fmaf(vs.x, vs.x, nS0); nS1 = fmaf(vs.y, vs.y, nS1);
        nS2 = fmaf(vs.z, vs.z, nS2); nS3 = fmaf(vs.w, vs.w, nS3);
        dS0 = fmaf(vs.x, mS, dS0);   dS1 = fmaf(vs.y, mS, dS1);
        dS2 = fmaf(vs.z, mS, dS2);   dS3 = fmaf(vs.w, mS, dS3);
        nT0 = fmaf(vt.x, vt.x, nT0); nT1 = fmaf(vt.y, vt.y, nT1);
        nT2 = fmaf(vt.z, vt.z, nT2); nT3 = fmaf(vt.w, vt.w, nT3);
        dT0 = fmaf(vt.x, mT, dT0);   dT1 = fmaf(vt.y, mT, dT1);
        dT2 = fmaf(vt.z, mT, dT2);   dT3 = fmaf(vt.w, mT, dT3);
    }

    const float e0 = __expf(s0 * dS0 * rsqrtf(fmaxf(nS0, 1e-24f)))
                   - __expf(s0 * dT0 * rsqrtf(fmaxf(nT0, 1e-24f)));
    const float e1 = __expf(s1 * dS1 * rsqrtf(fmaxf(nS1, 1e-24f)))
                   - __expf(s1 * dT1 * rsqrtf(fmaxf(nT1, 1e-24f)));
    const float e2 = __expf(s2 * dS2 * rsqrtf(fmaxf(nS2, 1e-24f)))
                   - __expf(s2 * dT2 * rsqrtf(fmaxf(nT2, 1e-24f)));
    const float e3 = __expf(s3 * dS3 * rsqrtf(fmaxf(nS3, 1e-24f)))
                   - __expf(s3 * dT3 * rsqrtf(fmaxf(nT3, 1e-24f)));
    float acc = fmaf(e0, e0, e1 * e1) + fmaf(e2, e2, e3 * e3);

    // Block reduce MSE partial, then last-block final reduction.
    __shared__ float smse[THR / 32];
    acc = wred(acc);
    const int lane = tid & 31, w = tid >> 5;
    if (lane == 0) smse[w] = acc;
    __syncthreads();
    const int gid = b * T3 + tile;
    if (tid == 0) {
        float sv = 0.f;
#pragma unroll
        for (int ww = 0; ww < THR / 32; ww++) sv += smse[ww];
        g_msep[gid] = sv;
        __threadfence();
        const unsigned int old = atomicAdd(&g_done, 1u);
        slast = (old == (unsigned int)(Bn * T3 - 1)) ? 1u : 0u;
    }
    __syncthreads();

    if (slast) {
        volatile float* mp = &g_msep[0];
        double d = 0.0;
#pragma unroll
        for (int k = 0; k < (Bn * T3) / THR; k++)
            d += (double)mp[tid * ((Bn * T3) / THR) + k];
        d = wredd(d);
        __shared__ double sd[THR / 32];
        if (lane == 0) sd[w] = d;
        __syncthreads();
        if (tid == 0) {
            double tot = 0.0;
#pragma unroll
            for (int ww = 0; ww < THR / 32; ww++) tot += sd[ww];
            out[0] = (float)(tot * (1.0 / ((double)Bn * (double)HWn)));
            g_done = 0;   // reset for next graph replay
        }
    }
}

extern "C" void kernel_launch(void* const* d_in, const int* in_sizes, int n_in,
                              void* d_out, int out_size) {
    const float* S  = (const float*)d_in[0];
    const float* T  = (const float*)d_in[1];
    const int*   TW = (const int*)d_in[2];
    float* out = (float*)d_out;

    // pass1: normal launch.
    dim3 g1(T1, Bn, 2);
    pass1_kernel<<<g1, THR>>>(S, T, TW);

    // finalize + pass3: programmatic dependent launches.
    cudaLaunchAttribute attr[1];
    attr[0].id = cudaLaunchAttributeProgrammaticStreamSerialization;
    attr[0].val.programmaticStreamSerializationAllowed = 1;

    {
        cudaLaunchConfig_t cfg = {};
        cfg.gridDim = dim3(Bn, 2);
        cfg.blockDim = dim3(256);
        cfg.attrs = attr;
        cfg.numAttrs = 1;
        cudaLaunchKernelEx(&cfg, finalize_kernel);
    }
    {
        cudaLaunchConfig_t cfg = {};
        cfg.gridDim = dim3(T3, Bn);
        cfg.blockDim = dim3(THR);
        cfg.attrs = attr;
        cfg.numAttrs = 1;
        cudaLaunchKernelEx(&cfg, pass3_kernel, S, T, TW, out);
    }
}

// round 17
// speedup vs baseline: 1.0889x; 1.0032x over previous
#include <cuda_runtime.h>
#include <math.h>

// Problem constants
#define Bn   32
#define Cn   16
#define HWn  65536
#define T1   128               // tiles per batch, pass1 (512 px/tile)
#define T3   128               // tiles per batch, pass3 (512 px/tile)
#define PPB  512               // pixels per block
#define THR  128               // threads per block; 4 px/thread, float4

// Scratch (__device__ globals; fully overwritten each run)
__device__ float g_part[2][Bn][32][T1];   // [tensor][batch][slot:0-15 tot,16-31 cls0][tile]
__device__ float g_cnt[Bn][T1];           // class-0 count partials (z==0)
__device__ float g_dm[2][Bn][Cn];         // normalized mean difference vectors
__device__ float g_msep[Bn * T3];         // per-block MSE partials
__device__ int   g_is32;                  // target dtype flag (written by pass1)
__device__ unsigned int g_done;           // last-block counter (self-resetting)

__device__ __forceinline__ float wred(float v) {
    v += __shfl_down_sync(0xFFFFFFFFu, v, 16);
    v += __shfl_down_sync(0xFFFFFFFFu, v, 8);
    v += __shfl_down_sync(0xFFFFFFFFu, v, 4);
    v += __shfl_down_sync(0xFFFFFFFFu, v, 2);
    v += __shfl_down_sync(0xFFFFFFFFu, v, 1);
    return v;
}
__device__ __forceinline__ double wredd(double v) {
    v += __shfl_down_sync(0xFFFFFFFFu, v, 16);
    v += __shfl_down_sync(0xFFFFFFFFu, v, 8);
    v += __shfl_down_sync(0xFFFFFFFFu, v, 4);
    v += __shfl_down_sync(0xFFFFFFFFu, v, 2);
    v += __shfl_down_sync(0xFFFFFFFFu, v, 1);
    return v;
}
__device__ __forceinline__ float4 ldg4(const float* p) {
    return __ldg((const float4*)p);     // default caching: lands in L1
}
__device__ __forceinline__ float4 ldcs4(const float* p) {
    return __ldcs((const float4*)p);    // streaming (pass3 only; no re-read)
}

// Per-block dtype sniff (pass1 only): int64 targets with values in {0,1} have
// all odd 32-bit words zero; int32 targets have random labels there (P(all
// 128 words zero) = 2^-128). All blocks read the same words (L2-broadcast).
__device__ __forceinline__ int sniff_is32(const int* __restrict__ tw, int tid) {
    int any = 0;
    if (tid < 128) any = tw[2 * tid + 1];
    return __syncthreads_or(any);
}

__device__ __forceinline__ void load_cls4(const int* __restrict__ twb, int p, int is32,
                                          int& c0, int& c1, int& c2, int& c3) {
    if (is32) {
        int4 v = __ldg((const int4*)(twb + p));
        c0 = v.x; c1 = v.y; c2 = v.z; c3 = v.w;
    } else {
        int4 a = __ldg((const int4*)(twb + 2 * p));
        int4 b = __ldg((const int4*)(twb + 2 * p + 4));
        c0 = a.x; c1 = a.z; c2 = b.x; c3 = b.z;
    }
}

// ---------------------------------------------------------------------------
// Pass 1 (streaming, genuine L1 re-read): loop 1 streams channels computing
// norms; pointer laundering defeats CSE so loop 2 re-loads from L1 and
// reduces each channel inline. No held tile -> ~50 regs -> 6 blocks/SM.
// grid (T1, Bn, 2); 4 px/thread, float4.
// ---------------------------------------------------------------------------
__global__ void __launch_bounds__(THR, 6)
pass1_kernel(const float* __restrict__ S, const float* __restrict__ T,
             const int* __restrict__ TW) {
    const int tile = blockIdx.x, b = blockIdx.y, z = blockIdx.z;
    const int tid  = threadIdx.x;
    const int lane = tid & 31, w = tid >> 5;
    const int is32 = sniff_is32(TW, tid);
    if (tid == 0) g_is32 = is32;   // same value from every block (benign race)

    const float* Xb  = (z ? T : S) + ((size_t)b << 20);
    const int*   twb = TW + (is32 ? ((size_t)b << 16) : ((size_t)b << 17));

    const int p = tile * PPB + tid * 4;
    int c0, c1, c2, c3;
    load_cls4(twb, p, is32, c0, c1, c2, c3);
    const float m0 = (c0 == 0) ? 1.f : 0.f;
    const float m1 = (c1 == 0) ? 1.f : 0.f;
    const float m2 = (c2 == 0) ? 1.f : 0.f;
    const float m3 = (c3 == 0) ? 1.f : 0.f;
    float cnt = (m0 + m1) + (m2 + m3);

    // Loop 1: streaming norm accumulation (caching loads -> L1 resident).
    float n0 = 0.f, n1 = 0.f, n2 = 0.f, n3 = 0.f;
#pragma unroll
    for (int c = 0; c < Cn; c++) {
        const float4 v = ldg4(Xb + ((size_t)c << 16) + p);
        n0 = fmaf(v.x, v.x, n0); n1 = fmaf(v.y, v.y, n1);
        n2 = fmaf(v.z, v.z, n2); n3 = fmaf(v.w, v.w, n3);
    }
    const float i0 = rsqrtf(fmaxf(n0, 1e-24f));
    const float i1 = rsqrtf(fmaxf(n1, 1e-24f));
    const float i2 = rsqrtf(fmaxf(n2, 1e-24f));
    const float i3 = rsqrtf(fmaxf(n3, 1e-24f));

    // Launder the pointer: compiler can no longer CSE loop-2 loads with
    // loop-1 loads, so the tile is never held in registers.
    asm volatile("" : "+l"(Xb));

    // Loop 2: re-read from L1 (~39 cyc hits), reduce each channel inline.
    __shared__ float sred[THR / 32][33];
#pragma unroll
    for (int c = 0; c < Cn; c++) {
        const float4 v = ldg4(Xb + ((size_t)c << 16) + p);
        const float f0 = v.x * i0, f1 = v.y * i1;
        const float f2 = v.z * i2, f3 = v.w * i3;
        float at = (f0 + f1) + (f2 + f3);
        float a0 = (m0 * f0 + m1 * f1) + (m2 * f2 + m3 * f3);
        at = wred(at); a0 = wred(a0);
        if (lane == 0) { sred[w][c] = at; sred[w][16 + c] = a0; }
    }
    cnt = wred(cnt);
    if (lane == 0) sred[w][32] = cnt;
    __syncthreads();
    if (tid < 33) {
        float s = 0.f;
#pragma unroll
        for (int ww = 0; ww < THR / 32; ww++) s += sred[ww][tid];
        if (tid < 32)      g_part[z][b][tid][tile] = s;
        else if (z == 0)   g_cnt[b][tile] = s;
    }
}

// ---------------------------------------------------------------------------
// Finalize (PDL secondary): waits on pass1, reduces tile partials -> dM.
// grid (Bn, 2), 256 threads.
// ---------------------------------------------------------------------------
__global__ void finalize_kernel() {
    cudaGridDependencySynchronize();

    const int b = blockIdx.x, z = blockIdx.y;
    const int tid = threadIdx.x;

    __shared__ float s[8][32];
    __shared__ float sc[8];
    __shared__ float red[32];
    __shared__ float scnt;
    __shared__ float smean[2][Cn];
    __shared__ float srn[2];

    {   // 256 threads = 32 slots x 8 groups of 16 tiles
        const int slot = tid & 31, g = tid >> 5;
        const float* base = &g_part[z][b][slot][0] + g * 16;
        float a = 0.f;
#pragma unroll
        for (int k = 0; k < 4; k++) {
            const float4 v = *(const float4*)(base + 4 * k);
            a += (v.x + v.y) + (v.z + v.w);
        }
        s[g][slot] = a;
    }
    if (tid < 8) {
        const float* cb = &g_cnt[b][0] + tid * 16;
        float a = 0.f;
#pragma unroll
        for (int k = 0; k < 4; k++) {
            const float4 v = *(const float4*)(cb + 4 * k);
            a += (v.x + v.y) + (v.z + v.w);
        }
        sc[tid] = a;
    }
    __syncthreads();
    if (tid < 32) {
        float a = 0.f;
#pragma unroll
        for (int g = 0; g < 8; g++) a += s[g][tid];
        red[tid] = a;
    } else if (tid == 32) {
        float a = 0.f;
#pragma unroll
        for (int g = 0; g < 8; g++) a += sc[g];
        scnt = a;
    }
    __syncthreads();
    if (tid < 2) {
        const int cls = tid;
        const float cnt0 = scnt;
        const float cnt  = cls ? ((float)HWn - cnt0) : cnt0;
        const float inv  = 1.0f / (cnt + 1e-6f);
        float nm2 = 0.f;
#pragma unroll
        for (int c = 0; c < Cn; c++) {
            const float tot = red[c], s0 = red[16 + c];
            const float sv  = cls ? (tot - s0) : s0;
            const float m   = sv * inv;
            smean[cls][c] = m;
            nm2 = fmaf(m, m, nm2);
        }
        srn[cls] = 1.0f / fmaxf(sqrtf(nm2), 1e-8f);
    }
    __syncthreads();
    if (tid < Cn) {
        g_dm[z][b][tid] = smean[0][tid] * srn[0] - smean[1][tid] * srn[1];
    }
}

// ---------------------------------------------------------------------------
// Pass 3 (PDL secondary): interleaved S/T channel loop (32 outstanding
// LDG.128/thread); cd = dot(v,dM)*rsqrt(||v||^2); pcsim = exp(+-cd); MSE.
// grid (T3, Bn); 4 px/thread, float4 loads. (Unchanged from R16.)
// ---------------------------------------------------------------------------
__global__ void __launch_bounds__(THR, 8)
pass3_kernel(const float* __restrict__ S, const float* __restrict__ T,
             const int* __restrict__ TW, float* __restrict__ out) {
    cudaGridDependencySynchronize();

    const int tile = blockIdx.x, b = blockIdx.y;
    const int tid  = threadIdx.x;

    __shared__ float sdM[2][Cn];
    __shared__ int sis32;
    __shared__ unsigned int slast;
    if (tid < 32) {
        const int z = tid >> 4, c = tid & 15;
        sdM[z][c] = g_dm[z][b][c];
    } else if (tid == 32) {
        sis32 = g_is32;
    }
    __syncthreads();
    const int is32 = sis32;

    const float* Sb  = S + ((size_t)b << 20);
    const float* Tb  = T + ((size_t)b << 20);
    const int*   twb = TW + (is32 ? ((size_t)b << 16) : ((size_t)b << 17));

    const int p = tile * PPB + tid * 4;
    int c0, c1, c2, c3;
    load_cls4(twb, p, is32, c0, c1, c2, c3);
    const float s0 = (c0 == 0) ? 1.f : -1.f;
    const float s1 = (c1 == 0) ? 1.f : -1.f;
    const float s2 = (c2 == 0) ? 1.f : -1.f;
    const float s3 = (c3 == 0) ? 1.f : -1.f;

    float nS0 = 0.f, nS1 = 0.f, nS2 = 0.f, nS3 = 0.f;
    float dS0 = 0.f, dS1 = 0.f, dS2 = 0.f, dS3 = 0.f;
    float nT0 = 0.f, nT1 = 0.f, nT2 = 0.f, nT3 = 0.f;
    float dT0 = 0.f, dT1 = 0.f, dT2 = 0.f, dT3 = 0.f;
#pragma unroll
    for (int c = 0; c < Cn; c++) {
        const float4 vs = ldcs4(Sb + ((size_t)c << 16) + p);
        const float4 vt = ldcs4(Tb + ((size_t)c << 16) + p);
        const float mS = sdM[0][c], mT = sdM[1][c];
        nS0 = fmaf(vs.x, vs.x, nS0); nS1 = fmaf(vs.y, vs.y, nS1);
        nS2 = fmaf(vs.z, vs.z, nS2); nS3 = fmaf(vs.w, vs.w, nS3);
        dS0 = fmaf(vs.x, mS, dS0);   dS1 = fmaf(vs.y, mS, dS1);
        dS2 = fmaf(vs.z, mS, dS2);   dS3 = fmaf(vs.w, mS, dS3);
        nT0 = fmaf(vt.x, vt.x, nT0); nT1 = fmaf(vt.y, vt.y, nT1);
        nT2 = fmaf(vt.z, vt.z, nT2); nT3 = fmaf(vt.w, vt.w, nT3);
        dT0 = fmaf(vt.x, mT, dT0);   dT1 = fmaf(vt.y, mT, dT1);
        dT2 = fmaf(vt.z, mT, dT2);   dT3 = fmaf(vt.w, mT, dT3);
    }

    const float e0 = __expf(s0 * dS0 * rsqrtf(fmaxf(nS0, 1e-24f)))
                   - __expf(s0 * dT0 * rsqrtf(fmaxf(nT0, 1e-24f)));
    const float e1 = __expf(s1 * dS1 * rsqrtf(fmaxf(nS1, 1e-24f)))
                   - __expf(s1 * dT1 * rsqrtf(fmaxf(nT1, 1e-24f)));
    const float e2 = __expf(s2 * dS2 * rsqrtf(fmaxf(nS2, 1e-24f)))
                   - __expf(s2 * dT2 * rsqrtf(fmaxf(nT2, 1e-24f)));
    const float e3 = __expf(s3 * dS3 * rsqrtf(fmaxf(nS3, 1e-24f)))
                   - __expf(s3 * dT3 * rsqrtf(fmaxf(nT3, 1e-24f)));
    float acc = fmaf(e0, e0, e1 * e1) + fmaf(e2, e2, e3 * e3);

    // Block reduce MSE partial, then last-block final reduction.
    __shared__ float smse[THR / 32];
    acc = wred(acc);
    const int lane = tid & 31, w = tid >> 5;
    if (lane == 0) smse[w] = acc;
    __syncthreads();
    const int gid = b * T3 + tile;
    if (tid == 0) {
        float sv = 0.f;
#pragma unroll
        for (int ww = 0; ww < THR / 32; ww++) sv += smse[ww];
        g_msep[gid] = sv;
        __threadfence();
        const unsigned int old = atomicAdd(&g_done, 1u);
        slast = (old == (unsigned int)(Bn * T3 - 1)) ? 1u : 0u;
    }
    __syncthreads();

    if (slast) {
        volatile float* mp = &g_msep[0];
        double d = 0.0;
#pragma unroll
        for (int k = 0; k < (Bn * T3) / THR; k++)
            d += (double)mp[tid * ((Bn * T3) / THR) + k];
        d = wredd(d);
        __shared__ double sd[THR / 32];
        if (lane == 0) sd[w] = d;
        __syncthreads();
        if (tid == 0) {
            double tot = 0.0;
#pragma unroll
            for (int ww = 0; ww < THR / 32; ww++) tot += sd[ww];
            out[0] = (float)(tot * (1.0 / ((double)Bn * (double)HWn)));
            g_done = 0;   // reset for next graph replay
        }
    }
}

extern "C" void kernel_launch(void* const* d_in, const int* in_sizes, int n_in,
                              void* d_out, int out_size) {
    const float* S  = (const float*)d_in[0];
    const float* T  = (const float*)d_in[1];
    const int*   TW = (const int*)d_in[2];
    float* out = (float*)d_out;

    // pass1: normal launch.
    dim3 g1(T1, Bn, 2);
    pass1_kernel<<<g1, THR>>>(S, T, TW);

    // finalize + pass3: programmatic dependent launches.
    cudaLaunchAttribute attr[1];
    attr[0].id = cudaLaunchAttributeProgrammaticStreamSerialization;
    attr[0].val.programmaticStreamSerializationAllowed = 1;

    {
        cudaLaunchConfig_t cfg = {};
        cfg.gridDim = dim3(Bn, 2);
        cfg.blockDim = dim3(256);
        cfg.attrs = attr;
        cfg.numAttrs = 1;
        cudaLaunchKernelEx(&cfg, finalize_kernel);
    }
    {
        cudaLaunchConfig_t cfg = {};
        cfg.gridDim = dim3(T3, Bn);
        cfg.blockDim = dim3(THR);
        cfg.attrs = attr;
        cfg.numAttrs = 1;
        cudaLaunchKernelEx(&cfg, pass3_kernel, S, T, TW, out);
    }
}